// round 13
// baseline (speedup 1.0000x reference)
#include <cuda_runtime.h>
#include <cuda_fp16.h>
#include <cstdint>

// GAPooling: out[b,n,c] = (1/K) * sum_k x[b, idx[b,n,k], c]
// x [16,4096,64] fp32, idx [16,4096,32] int32, out fp32.
//
// Stage 1: x -> fp16 table (8 MB). Row = 128 B = exactly one L1 line.
// Stage 2: warp per point; 8x LDG.128 gathers (4 whole rows each), per-lane
//          idx loads (warp's index stream = one 128 B line, zero SHFL on
//          the LSU path), hadd2 chains of 4 with fp32 spill, butterfly
//          reduce, coalesced store.
// NEW (R13): CTA->SM BATCH AFFINITY. Placement is LUT[bid % nSM], so all
// bids with equal residue land on the same SM. grid = nSM*8 (single wave,
// all CTAs resident), batch = (bid % nSM) % 16 -> every CTA resident on an
// SM works the SAME batch. Per-SM line reuse rises ~1.4x -> ~3.5x refs per
// line, roughly doubling the L1 hit rate (policy couldn't do this; only
// scheduling can). Each CTA loops over its batch's point-groups.

static constexpr int B = 16;
static constexpr int N = 4096;
static constexpr int C = 64;
static constexpr int K = 32;
static constexpr int GROUPS = N / 8;         // 512 groups of 8 points/batch

__device__ __half g_xh[(size_t)B * N * C];   // 8 MB fp16 table

__global__ __launch_bounds__(256) void cvt_kernel(const float* __restrict__ x)
{
    const int t = blockIdx.x * blockDim.x + threadIdx.x;   // B*N*C/8 threads
    const float4* __restrict__ xi = reinterpret_cast<const float4*>(x);
    float4 a = xi[2 * t];
    float4 b = xi[2 * t + 1];
    __half2 h[4];
    h[0] = __floats2half2_rn(a.x, a.y);
    h[1] = __floats2half2_rn(a.z, a.w);
    h[2] = __floats2half2_rn(b.x, b.y);
    h[3] = __floats2half2_rn(b.z, b.w);
    reinterpret_cast<uint4*>(g_xh)[t] = *reinterpret_cast<uint4*>(h);
}

__global__ __launch_bounds__(256, 8) void gap_f16_kernel(
    const int* __restrict__ idx,
    float* __restrict__ out,
    int nsm)
{
    const int bid  = blockIdx.x;
    const int wid  = threadIdx.x >> 5;
    const int lane = threadIdx.x & 31;

    // Residue-based affinity: all CTAs with the same r sit on the same SM.
    const int r_sm  = bid % nsm;
    const int kslot = bid / nsm;             // 0..7 (co-resident CTA slot)
    const int batch = r_sm % B;              // SM-pinned batch
    const int w16   = r_sm / B;              // which residue-group of batch
    const int extra = nsm % B;
    const int nres  = nsm / B + (batch < extra ? 1 : 0);
    const int slot   = w16 * 8 + kslot;      // this CTA's slot within batch
    const int nslots = nres * 8;

    const int rr = lane >> 3;                // 0..3  (row slot within LDG)
    const int cq = lane & 7;                 // 0..7  (16 B channel chunk)

    const __half* __restrict__ xb = g_xh + (size_t)batch * N * C + cq * 8;
    const float inv_k = 1.0f / (float)K;

    for (int g = slot; g < GROUPS; g += nslots) {
        const int point = batch * N + g * 8 + wid;

        // This lane's index stream: one 128 B line per warp.
        const int* __restrict__ iw = idx + (size_t)point * K + rr;

        float acc[8];
        #pragma unroll
        for (int c = 0; c < 8; c++) acc[c] = 0.f;

        #pragma unroll
        for (int blk = 0; blk < 2; blk++) {
            __half2 hacc[4];
            #pragma unroll
            for (int q = 0; q < 4; q++)
                hacc[q] = __half2half2(__ushort_as_half(0));

            #pragma unroll
            for (int i = 0; i < 4; i++) {
                const int j = __ldg(iw + (blk * 4 + i) * 4);
                const float4 raw = *reinterpret_cast<const float4*>(
                    xb + (size_t)j * C);                // 16 B = 8 halves
                const __half2* h2 = reinterpret_cast<const __half2*>(&raw);
                #pragma unroll
                for (int q = 0; q < 4; q++)
                    hacc[q] = __hadd2(hacc[q], h2[q]);
            }

            #pragma unroll
            for (int q = 0; q < 4; q++) {
                const float2 f = __half22float2(hacc[q]);
                acc[2 * q]     += f.x;
                acc[2 * q + 1] += f.y;
            }
        }

        // reduce the 4 row-slots (lane bits 3,4) in fp32
        #pragma unroll
        for (int c = 0; c < 8; c++) {
            acc[c] += __shfl_xor_sync(0xffffffffu, acc[c], 8);
            acc[c] += __shfl_xor_sync(0xffffffffu, acc[c], 16);
        }

        if (rr == 0) {
            float4 o0, o1;
            o0.x = acc[0] * inv_k; o0.y = acc[1] * inv_k;
            o0.z = acc[2] * inv_k; o0.w = acc[3] * inv_k;
            o1.x = acc[4] * inv_k; o1.y = acc[5] * inv_k;
            o1.z = acc[6] * inv_k; o1.w = acc[7] * inv_k;
            float4* op = reinterpret_cast<float4*>(
                out + (size_t)point * C + cq * 8);
            op[0] = o0;
            op[1] = o1;
        }
    }
}

extern "C" void kernel_launch(void* const* d_in, const int* in_sizes, int n_in,
                              void* d_out, int out_size)
{
    // Select inputs by element count (ordering-proof):
    //   x:   B*N*C = 4,194,304 ; idx: B*N*K = 2,097,152
    const float* x = nullptr;
    const int* idx = nullptr;
    for (int i = 0; i < n_in; i++) {
        if (in_sizes[i] == B * N * C) x = (const float*)d_in[i];
        else if (in_sizes[i] == B * N * K) idx = (const int*)d_in[i];
    }
    if (!x) x = (const float*)d_in[0];
    if (!idx) idx = (const int*)d_in[1];
    float* out = (float*)d_out;

    // One-time: SM count (152 on GB300) for the affinity mapping.
    static int nsm = 0;
    if (!nsm) {
        cudaDeviceGetAttribute(&nsm, cudaDevAttrMultiProcessorCount, 0);
        if (nsm <= 0) nsm = 148;
        cudaFuncSetAttribute(gap_f16_kernel,
                             cudaFuncAttributePreferredSharedMemoryCarveout, 0);
    }

    // Stage 1: fp32 -> fp16 table
    const int cvt_threads = (B * N * C) / 8;               // 524288
    cvt_kernel<<<cvt_threads / 256, 256>>>(x);

    // Stage 2: single wave of nsm*8 CTAs, batch-affine residues.
    gap_f16_kernel<<<nsm * 8, 256>>>(idx, out, nsm);
}

// round 14
// speedup vs baseline: 1.2528x; 1.2528x over previous
#include <cuda_runtime.h>
#include <cuda_fp16.h>
#include <cstdint>

// GAPooling: out[b,n,c] = (1/K) * sum_k x[b, idx[b,n,k], c]
// x [16,4096,64] fp32, idx [16,4096,32] int32, out fp32.
//
// Stage 1: x -> fp16 table (8 MB). Row = 128 B = exactly one L1 line.
// Stage 2: warp per point; 8x LDG.128 gathers (4 whole rows each -- the
//          wavefront-optimal shape: 1 line per gathered row, max bytes per
//          LDG instruction), per-lane idx loads (the warp's whole index
//          stream lives in one 128 B line; zero SHFL on the LSU/MIO path),
//          hadd2 chains of 4 with fp32 spill, butterfly reduce over the 4
//          row-slots, coalesced fp32 store.
// Preferred-carveout 0 -> maximize L1D (smem unused).
// Flat launch: chunk-pipelining (R10), evict policies (R11), persistent
// batch-affinity (R13) all regressed; this is the measured optimum shape.

static constexpr int B = 16;
static constexpr int N = 4096;
static constexpr int C = 64;
static constexpr int K = 32;

__device__ __half g_xh[(size_t)B * N * C];   // 8 MB fp16 table

__global__ __launch_bounds__(256) void cvt_kernel(const float* __restrict__ x)
{
    const int t = blockIdx.x * blockDim.x + threadIdx.x;   // B*N*C/8 threads
    const float4* __restrict__ xi = reinterpret_cast<const float4*>(x);
    float4 a = xi[2 * t];
    float4 b = xi[2 * t + 1];
    __half2 h[4];
    h[0] = __floats2half2_rn(a.x, a.y);
    h[1] = __floats2half2_rn(a.z, a.w);
    h[2] = __floats2half2_rn(b.x, b.y);
    h[3] = __floats2half2_rn(b.z, b.w);
    reinterpret_cast<uint4*>(g_xh)[t] = *reinterpret_cast<uint4*>(h);
}

__global__ __launch_bounds__(256) void gap_f16_kernel(
    const int* __restrict__ idx,
    float* __restrict__ out)
{
    const int warp_global = (blockIdx.x * blockDim.x + threadIdx.x) >> 5;
    const int lane = threadIdx.x & 31;

    const int b  = warp_global >> 12;          // N = 4096 = 2^12
    const int r  = lane >> 3;                  // 0..3  (row slot within LDG)
    const int cq = lane & 7;                   // 0..7  (16 B channel chunk)

    // This lane's index stream: positions r, r+4, ..., r+28. One 128 B line.
    const int* __restrict__ iw = idx + (size_t)warp_global * K + r;

    const __half* __restrict__ xb = g_xh + (size_t)b * N * C + cq * 8;

    float acc[8];
    #pragma unroll
    for (int c = 0; c < 8; c++) acc[c] = 0.f;

    #pragma unroll
    for (int blk = 0; blk < 2; blk++) {
        __half2 hacc[4];
        #pragma unroll
        for (int q = 0; q < 4; q++) hacc[q] = __half2half2(__ushort_as_half(0));

        #pragma unroll
        for (int i = 0; i < 4; i++) {
            const int j = __ldg(iw + (blk * 4 + i) * 4);   // slot r, quad i
            const float4 raw = *reinterpret_cast<const float4*>(
                xb + (size_t)j * C);                        // 16 B = 8 halves
            const __half2* h2 = reinterpret_cast<const __half2*>(&raw);
            #pragma unroll
            for (int q = 0; q < 4; q++)
                hacc[q] = __hadd2(hacc[q], h2[q]);
        }

        #pragma unroll
        for (int q = 0; q < 4; q++) {
            const float2 f = __half22float2(hacc[q]);
            acc[2 * q]     += f.x;
            acc[2 * q + 1] += f.y;
        }
    }

    // reduce the 4 r-groups (lane bits 3,4) in fp32
    #pragma unroll
    for (int c = 0; c < 8; c++) {
        acc[c] += __shfl_xor_sync(0xffffffffu, acc[c], 8);
        acc[c] += __shfl_xor_sync(0xffffffffu, acc[c], 16);
    }

    if (r == 0) {
        const float inv_k = 1.0f / (float)K;
        float4 o0, o1;
        o0.x = acc[0] * inv_k; o0.y = acc[1] * inv_k;
        o0.z = acc[2] * inv_k; o0.w = acc[3] * inv_k;
        o1.x = acc[4] * inv_k; o1.y = acc[5] * inv_k;
        o1.z = acc[6] * inv_k; o1.w = acc[7] * inv_k;
        float4* op = reinterpret_cast<float4*>(
            out + (size_t)warp_global * C + cq * 8);
        op[0] = o0;
        op[1] = o1;
    }
}

extern "C" void kernel_launch(void* const* d_in, const int* in_sizes, int n_in,
                              void* d_out, int out_size)
{
    // Select inputs by element count (ordering-proof):
    //   x:   B*N*C = 4,194,304 ; idx: B*N*K = 2,097,152
    const float* x = nullptr;
    const int* idx = nullptr;
    for (int i = 0; i < n_in; i++) {
        if (in_sizes[i] == B * N * C) x = (const float*)d_in[i];
        else if (in_sizes[i] == B * N * K) idx = (const int*)d_in[i];
    }
    if (!x) x = (const float*)d_in[0];
    if (!idx) idx = (const int*)d_in[1];
    float* out = (float*)d_out;

    // One-time: request 0% smem carveout -> maximum L1D for the gather.
    static bool attr_done = false;
    if (!attr_done) {
        cudaFuncSetAttribute(gap_f16_kernel,
                             cudaFuncAttributePreferredSharedMemoryCarveout, 0);
        attr_done = true;
    }

    // Stage 1: fp32 -> fp16 table
    const int cvt_threads = (B * N * C) / 8;               // 524288
    cvt_kernel<<<cvt_threads / 256, 256>>>(x);

    // Stage 2: gather-mean, one warp per point (exact grid, no tail)
    const int total_warps = B * N;                          // 65536
    gap_f16_kernel<<<(total_warps * 32) / 256, 256>>>(idx, out);
}